// round 3
// baseline (speedup 1.0000x reference)
#include <cuda_runtime.h>
#include <math.h>
#include <stdint.h>

// ---------------------------------------------------------------------------
// Problem constants
// ---------------------------------------------------------------------------
namespace {
constexpr int B_   = 8;
constexpr int T_   = 1024;
constexpr int E_   = 512;
constexpr int NH_  = 8;
constexpr int HD_  = 64;
constexpr int NT_  = B_ * T_;          // 8192 tokens
constexpr int QKV_ = 3 * E_;           // 1536
constexpr int LBL_ = 64;
constexpr int D_   = E_ + LBL_;        // 576
constexpr int R_   = 16;
constexpr int FF1_ = 256;
constexpr int P_   = 12;
constexpr int NP_  = 24;               // 2P tokens gathered per batch
constexpr int NPAIR_ = 276;            // C(24,2)
constexpr int TP_  = B_ * NPAIR_;      // 2208 pairs
constexpr int F2_  = 2 * FF1_ + 1 + R_; // 529
constexpr float EPS_ = 1e-5f;
constexpr int FA_SMEM_ = 3 * 64 * 68 * (int)sizeof(float);  // 52224 bytes
}

// ---------------------------------------------------------------------------
// Scratch (device globals — no allocation allowed)
// ---------------------------------------------------------------------------
__device__ float g_x  [NT_ * E_];
__device__ float g_qkv[NT_ * QKV_];
__device__ float g_att[NT_ * E_];
__device__ float g_y  [NT_ * E_];
__device__ float g_h  [NT_ * E_];
__device__ float g_bps[128 * E_];
__device__ float g_bpq[128 * E_];
__device__ float g_bsum[E_];
__device__ float g_bsq [E_];
__device__ float g_emb[B_ * NP_ * D_];
__device__ float g_H  [B_ * NP_ * FF1_];
__device__ float g_nrm[B_ * NP_];
__device__ float g_mdiag[R_ * D_];
__device__ float g_bce[TP_];

// ---------------------------------------------------------------------------
// Helpers
// ---------------------------------------------------------------------------
__device__ __forceinline__ float warp_sum(float v) {
#pragma unroll
    for (int off = 16; off; off >>= 1)
        v += __shfl_xor_sync(0xffffffffu, v, off);
    return v;
}

// ---------------------------------------------------------------------------
// SGEMM: C[M,N] = A[M,K] * B[N,K]^T + bias  (optional ReLU)
// BM=BN=128, BK=16, 256 threads, 8x8 per thread. M,N multiples of 128,
// K multiple of 16 (all true here).
// ---------------------------------------------------------------------------
template <bool RELU>
__global__ __launch_bounds__(256) void sgemm_bias(
    const float* __restrict__ A, const float* __restrict__ Bm,
    const float* __restrict__ bias, float* __restrict__ C,
    int M, int N, int K)
{
    __shared__ float As[16][128];
    __shared__ float Bs[16][128];
    const int tid = threadIdx.x;
    const int tx = tid & 15, ty = tid >> 4;
    const int bm = blockIdx.y << 7, bn = blockIdx.x << 7;
    const int lrow = tid >> 1;
    const int lk   = (tid & 1) << 2;
    const float* Ap = A  + (size_t)(bm + lrow) * K + lk;
    const float* Bp = Bm + (size_t)(bn + lrow) * K + lk;

    float acc[8][8];
#pragma unroll
    for (int i = 0; i < 8; i++)
#pragma unroll
        for (int j = 0; j < 8; j++) acc[i][j] = 0.f;

    for (int k0 = 0; k0 < K; k0 += 16) {
        float4 a0 = *(const float4*)(Ap + k0);
        float4 a1 = *(const float4*)(Ap + k0 + 8);
        float4 b0 = *(const float4*)(Bp + k0);
        float4 b1 = *(const float4*)(Bp + k0 + 8);
        __syncthreads();
        As[lk+0][lrow]=a0.x; As[lk+1][lrow]=a0.y; As[lk+2][lrow]=a0.z; As[lk+3][lrow]=a0.w;
        As[lk+8][lrow]=a1.x; As[lk+9][lrow]=a1.y; As[lk+10][lrow]=a1.z; As[lk+11][lrow]=a1.w;
        Bs[lk+0][lrow]=b0.x; Bs[lk+1][lrow]=b0.y; Bs[lk+2][lrow]=b0.z; Bs[lk+3][lrow]=b0.w;
        Bs[lk+8][lrow]=b1.x; Bs[lk+9][lrow]=b1.y; Bs[lk+10][lrow]=b1.z; Bs[lk+11][lrow]=b1.w;
        __syncthreads();
#pragma unroll
        for (int kk = 0; kk < 16; kk++) {
            float4 ra0 = *(const float4*)&As[kk][ty << 3];
            float4 ra1 = *(const float4*)&As[kk][(ty << 3) + 4];
            float4 rb0 = *(const float4*)&Bs[kk][tx << 3];
            float4 rb1 = *(const float4*)&Bs[kk][(tx << 3) + 4];
            float ra[8] = {ra0.x, ra0.y, ra0.z, ra0.w, ra1.x, ra1.y, ra1.z, ra1.w};
            float rb[8] = {rb0.x, rb0.y, rb0.z, rb0.w, rb1.x, rb1.y, rb1.z, rb1.w};
#pragma unroll
            for (int i = 0; i < 8; i++)
#pragma unroll
                for (int j = 0; j < 8; j++)
                    acc[i][j] = fmaf(ra[i], rb[j], acc[i][j]);
        }
    }

    const int cn = bn + (tx << 3);
    float bsv[8];
#pragma unroll
    for (int j = 0; j < 8; j++) bsv[j] = bias[cn + j];
#pragma unroll
    for (int i = 0; i < 8; i++) {
        int row = bm + (ty << 3) + i;
        float v[8];
#pragma unroll
        for (int j = 0; j < 8; j++) {
            v[j] = acc[i][j] + bsv[j];
            if (RELU) v[j] = fmaxf(v[j], 0.f);
        }
        float4* out = (float4*)&C[(size_t)row * N + cn];
        out[0] = make_float4(v[0], v[1], v[2], v[3]);
        out[1] = make_float4(v[4], v[5], v[6], v[7]);
    }
}

// ---------------------------------------------------------------------------
// Flash attention, fp32. grid (T/64, NH, B), 256 threads.
// Dynamic smem: Qs[64][68] | KP[64][68] | Vs[64][68]  (52224 B).
// qkv layout: [token, 1536] with q|k|v slices; head h at col h*64.
// ---------------------------------------------------------------------------
__global__ __launch_bounds__(256) void flash_attn(const float* __restrict__ qkv,
                                                  float* __restrict__ out)
{
    extern __shared__ float fa_smem[];
    float (*Qs)[68] = (float(*)[68])fa_smem;            // [q][d]
    float (*KP)[68] = (float(*)[68])(fa_smem + 64*68);  // K^T [d][k], reused as P [q][k]
    float (*Vs)[68] = (float(*)[68])(fa_smem + 2*64*68);// [k][d]
    const int tid = threadIdx.x;
    const int tx = tid & 15, ty = tid >> 4;
    const int q0 = blockIdx.x << 6;
    const int h  = blockIdx.y;
    const int b  = blockIdx.z;
    const float* base = qkv + (size_t)b * T_ * QKV_;

#pragma unroll
    for (int it = 0; it < 4; it++) {
        int idx = tid + (it << 8);
        int r = idx >> 4, c = (idx & 15) << 2;
        float4 v = *(const float4*)(base + (size_t)(q0 + r) * QKV_ + h * HD_ + c);
        *(float4*)&Qs[r][c] = v;
    }

    float m[4], l[4], o[4][4];
#pragma unroll
    for (int i = 0; i < 4; i++) {
        m[i] = -1e30f; l[i] = 0.f;
#pragma unroll
        for (int j = 0; j < 4; j++) o[i][j] = 0.f;
    }

    for (int kt = 0; kt < 16; kt++) {
        const int k0 = kt << 6;
        __syncthreads();   // protect KP/Vs from previous iteration readers; first iter: Qs ready
#pragma unroll
        for (int it = 0; it < 4; it++) {
            int idx = tid + (it << 8);
            int r = idx >> 4, c = (idx & 15) << 2;
            const float* kr = base + (size_t)(k0 + r) * QKV_ + E_ + h * HD_ + c;
            float4 kv = *(const float4*)kr;
            KP[c+0][r] = kv.x; KP[c+1][r] = kv.y; KP[c+2][r] = kv.z; KP[c+3][r] = kv.w;
            float4 vv = *(const float4*)(kr + E_);
            *(float4*)&Vs[r][c] = vv;
        }
        __syncthreads();

        float s[4][4];
#pragma unroll
        for (int i = 0; i < 4; i++)
#pragma unroll
            for (int j = 0; j < 4; j++) s[i][j] = 0.f;

#pragma unroll 8
        for (int d = 0; d < 64; d++) {
            float a0 = Qs[(ty<<2)+0][d];
            float a1 = Qs[(ty<<2)+1][d];
            float a2 = Qs[(ty<<2)+2][d];
            float a3 = Qs[(ty<<2)+3][d];
            float4 bb = *(const float4*)&KP[d][tx << 2];
            s[0][0]=fmaf(a0,bb.x,s[0][0]); s[0][1]=fmaf(a0,bb.y,s[0][1]); s[0][2]=fmaf(a0,bb.z,s[0][2]); s[0][3]=fmaf(a0,bb.w,s[0][3]);
            s[1][0]=fmaf(a1,bb.x,s[1][0]); s[1][1]=fmaf(a1,bb.y,s[1][1]); s[1][2]=fmaf(a1,bb.z,s[1][2]); s[1][3]=fmaf(a1,bb.w,s[1][3]);
            s[2][0]=fmaf(a2,bb.x,s[2][0]); s[2][1]=fmaf(a2,bb.y,s[2][1]); s[2][2]=fmaf(a2,bb.z,s[2][2]); s[2][3]=fmaf(a2,bb.w,s[2][3]);
            s[3][0]=fmaf(a3,bb.x,s[3][0]); s[3][1]=fmaf(a3,bb.y,s[3][1]); s[3][2]=fmaf(a3,bb.z,s[3][2]); s[3][3]=fmaf(a3,bb.w,s[3][3]);
        }

#pragma unroll
        for (int i = 0; i < 4; i++) {
            float rm = -1e30f;
#pragma unroll
            for (int j = 0; j < 4; j++) { s[i][j] *= 0.125f; rm = fmaxf(rm, s[i][j]); }
#pragma unroll
            for (int off = 8; off; off >>= 1)
                rm = fmaxf(rm, __shfl_xor_sync(0xffffffffu, rm, off, 16));
            float mn = fmaxf(m[i], rm);
            float rs = 0.f;
#pragma unroll
            for (int j = 0; j < 4; j++) { s[i][j] = __expf(s[i][j] - mn); rs += s[i][j]; }
#pragma unroll
            for (int off = 8; off; off >>= 1)
                rs += __shfl_xor_sync(0xffffffffu, rs, off, 16);
            float corr = __expf(m[i] - mn);
            l[i] = l[i] * corr + rs;
            m[i] = mn;
#pragma unroll
            for (int j = 0; j < 4; j++) o[i][j] *= corr;
        }

        __syncthreads();   // all K reads of KP done
#pragma unroll
        for (int i = 0; i < 4; i++)
#pragma unroll
            for (int j = 0; j < 4; j++)
                KP[(ty<<2)+i][(tx<<2)+j] = s[i][j];
        __syncthreads();

#pragma unroll 8
        for (int d = 0; d < 64; d++) {
            float p0 = KP[(ty<<2)+0][d];
            float p1 = KP[(ty<<2)+1][d];
            float p2 = KP[(ty<<2)+2][d];
            float p3 = KP[(ty<<2)+3][d];
            float4 vv = *(const float4*)&Vs[d][tx << 2];
            o[0][0]=fmaf(p0,vv.x,o[0][0]); o[0][1]=fmaf(p0,vv.y,o[0][1]); o[0][2]=fmaf(p0,vv.z,o[0][2]); o[0][3]=fmaf(p0,vv.w,o[0][3]);
            o[1][0]=fmaf(p1,vv.x,o[1][0]); o[1][1]=fmaf(p1,vv.y,o[1][1]); o[1][2]=fmaf(p1,vv.z,o[1][2]); o[1][3]=fmaf(p1,vv.w,o[1][3]);
            o[2][0]=fmaf(p2,vv.x,o[2][0]); o[2][1]=fmaf(p2,vv.y,o[2][1]); o[2][2]=fmaf(p2,vv.z,o[2][2]); o[2][3]=fmaf(p2,vv.w,o[2][3]);
            o[3][0]=fmaf(p3,vv.x,o[3][0]); o[3][1]=fmaf(p3,vv.y,o[3][1]); o[3][2]=fmaf(p3,vv.z,o[3][2]); o[3][3]=fmaf(p3,vv.w,o[3][3]);
        }
    }

#pragma unroll
    for (int i = 0; i < 4; i++) {
        float inv = 1.f / l[i];
        float4 r = make_float4(o[i][0]*inv, o[i][1]*inv, o[i][2]*inv, o[i][3]*inv);
        *(float4*)&out[(size_t)(b * T_ + q0 + (ty<<2) + i) * E_ + h * HD_ + (tx<<2)] = r;
    }
}

// ---------------------------------------------------------------------------
// out = LayerNorm(x + y) * g + b   (one block per row, 128 threads)
// ---------------------------------------------------------------------------
__global__ __launch_bounds__(128) void add_ln(
    const float* __restrict__ x, const float* __restrict__ y,
    const float* __restrict__ g, const float* __restrict__ be,
    float* __restrict__ outp)
{
    const int row = blockIdx.x, tid = threadIdx.x;
    const int c4 = tid << 2;
    float4 xv = *(const float4*)&x[(size_t)row * E_ + c4];
    float4 yv = *(const float4*)&y[(size_t)row * E_ + c4];
    float v[4] = {xv.x + yv.x, xv.y + yv.y, xv.z + yv.z, xv.w + yv.w};
    float s = 0.f, q = 0.f;
#pragma unroll
    for (int c = 0; c < 4; c++) { s += v[c]; q = fmaf(v[c], v[c], q); }
    s = warp_sum(s); q = warp_sum(q);
    __shared__ float ws[4], wq[4];
    const int lane = tid & 31, w = tid >> 5;
    if (lane == 0) { ws[w] = s; wq[w] = q; }
    __syncthreads();
    s = ws[0] + ws[1] + ws[2] + ws[3];
    q = wq[0] + wq[1] + wq[2] + wq[3];
    const float mu   = s * (1.f / E_);
    const float var  = q * (1.f / E_) - mu * mu;
    const float rstd = rsqrtf(var + EPS_);
    float4 gv = *(const float4*)&g[c4];
    float4 bv = *(const float4*)&be[c4];
    float4 ov;
    ov.x = (v[0] - mu) * rstd * gv.x + bv.x;
    ov.y = (v[1] - mu) * rstd * gv.y + bv.y;
    ov.z = (v[2] - mu) * rstd * gv.z + bv.z;
    ov.w = (v[3] - mu) * rstd * gv.w + bv.w;
    *(float4*)&outp[(size_t)row * E_ + c4] = ov;
}

// ---------------------------------------------------------------------------
// Batch-norm stats over all 8192 rows, two deterministic stages
// ---------------------------------------------------------------------------
__global__ __launch_bounds__(256) void bn_part(const float* __restrict__ x) {
    const int blk = blockIdx.x, tid = threadIdx.x;
    float s0 = 0.f, q0 = 0.f, s1 = 0.f, q1 = 0.f;
    const size_t rb = (size_t)blk * 64 * E_;
    for (int r = 0; r < 64; r++) {
        float a = x[rb + (size_t)r * E_ + tid];
        float c = x[rb + (size_t)r * E_ + 256 + tid];
        s0 += a; q0 = fmaf(a, a, q0);
        s1 += c; q1 = fmaf(c, c, q1);
    }
    g_bps[blk * E_ + tid] = s0;        g_bpq[blk * E_ + tid] = q0;
    g_bps[blk * E_ + 256 + tid] = s1;  g_bpq[blk * E_ + 256 + tid] = q1;
}

__global__ void bn_final() {
    const int c = blockIdx.x * blockDim.x + threadIdx.x;   // 512 threads total
    float s = 0.f, q = 0.f;
    for (int p = 0; p < 128; p++) { s += g_bps[p * E_ + c]; q += g_bpq[p * E_ + c]; }
    g_bsum[c] = s; g_bsq[c] = q;
}

// ---------------------------------------------------------------------------
// Gather rep at the 24 tokens per batch: emb = [shared + bn(out), ner]
// grid (NP, B), 576 threads
// ---------------------------------------------------------------------------
__global__ void gather_emb(const float* __restrict__ sh, const float* __restrict__ ner,
                           const int* __restrict__ rs, const int* __restrict__ re,
                           const float* __restrict__ xw)
{
    const int j = blockIdx.x, b = blockIdx.y, d = threadIdx.x;
    const int t = (j < P_) ? rs[b * P_ + j] : re[b * P_ + j - P_];
    float v;
    if (d < E_) {
        float mu   = g_bsum[d] * (1.f / NT_);
        float var  = g_bsq[d] * (1.f / NT_) - mu * mu;
        float rstd = rsqrtf(var + EPS_);
        size_t off = ((size_t)b * T_ + t) * E_ + d;
        v = sh[off] + (xw[off] - mu) * rstd;
    } else {
        v = ner[((size_t)b * T_ + t) * LBL_ + (d - E_)];
    }
    g_emb[(b * NP_ + j) * D_ + d] = v;
}

// M is diag-constructed: extract diagonal once (off-diagonals are exactly 0)
__global__ void mdiag_k(const float* __restrict__ M) {
    const int r = blockIdx.x, d = threadIdx.x;
    g_mdiag[r * D_ + d] = M[((size_t)r * D_ + d) * D_ + d];
}

// ---------------------------------------------------------------------------
// H[b,j] = relu(W1 @ emb + b1), plus its norm. grid 192, 256 threads (8 warps)
// ---------------------------------------------------------------------------
__global__ __launch_bounds__(256) void rel_h(const float* __restrict__ w1,
                                             const float* __restrict__ b1)
{
    __shared__ float es[D_];
    __shared__ float Hs[FF1_];
    __shared__ float wsum[8];
    const int bj = blockIdx.x, tid = threadIdx.x, lane = tid & 31, w = tid >> 5;
    for (int d = tid; d < D_; d += 256) es[d] = g_emb[bj * D_ + d];
    __syncthreads();
    for (int f = w; f < FF1_; f += 8) {
        float acc = 0.f;
        const float* wr = w1 + (size_t)f * D_;
        for (int d = lane; d < D_; d += 32) acc = fmaf(wr[d], es[d], acc);
        acc = warp_sum(acc);
        if (lane == 0) Hs[f] = fmaxf(acc + b1[f], 0.f);
    }
    __syncthreads();
    float hv = Hs[tid];
    g_H[bj * FF1_ + tid] = hv;
    float q = warp_sum(hv * hv);
    if (lane == 0) wsum[w] = q;
    __syncthreads();
    if (tid == 0) {
        float ss = 0.f;
        for (int k = 0; k < 8; k++) ss += wsum[k];
        g_nrm[bj] = fmaxf(sqrtf(ss), 1e-8f);
    }
}

// ---------------------------------------------------------------------------
// Per-pair scores + BCE. grid 2208, 256 threads (8 warps)
// ---------------------------------------------------------------------------
__global__ __launch_bounds__(256) void pair_k(
    const int* __restrict__ rs, const int* __restrict__ re, const int* __restrict__ rq,
    const float* __restrict__ w2, const float* __restrict__ b2)
{
    const int bp = blockIdx.x;
    const int b = bp / NPAIR_, p = bp % NPAIR_;
    int i = 0, rem = p, cnt = NP_ - 1;
    while (rem >= cnt) { rem -= cnt; i++; cnt--; }
    const int j = i + 1 + rem;

    __shared__ float e1[D_], e2[D_], h1s[FF1_], h2s[FF1_];
    __shared__ float sdm[R_], sred[8], sbce[R_];
    __shared__ float scos;
    const int tid = threadIdx.x, lane = tid & 31, w = tid >> 5;
    const int bi = b * NP_ + i, bj = b * NP_ + j;

    for (int d = tid; d < D_; d += 256) { e1[d] = g_emb[bi * D_ + d]; e2[d] = g_emb[bj * D_ + d]; }
    h1s[tid] = g_H[bi * FF1_ + tid];
    h2s[tid] = g_H[bj * FF1_ + tid];
    __syncthreads();

    float pp = warp_sum(h1s[tid] * h2s[tid]);
    if (lane == 0) sred[w] = pp;
    __syncthreads();
    if (tid == 0) {
        float hh = 0.f;
        for (int k = 0; k < 8; k++) hh += sred[k];
        scos = hh / (g_nrm[bi] * g_nrm[bj]);
    }
    for (int r = w; r < R_; r += 8) {
        float acc = 0.f;
        for (int d = lane; d < D_; d += 32)
            acc = fmaf(g_mdiag[r * D_ + d], e1[d] * e2[d], acc);
        acc = warp_sum(acc);
        if (lane == 0) sdm[r] = acc;
    }
    __syncthreads();   // orders scos + sdm writes before readers below

    const int ti = (i < P_) ? rs[b * P_ + i] : re[b * P_ + i - P_];
    const int tj = (j < P_) ? rs[b * P_ + j] : re[b * P_ + j - P_];

    for (int r = w; r < R_; r += 8) {
        float acc = 0.f;
        for (int f = lane; f < F2_; f += 32) {
            float v = (f < FF1_)     ? h1s[f]
                    : (f < 2 * FF1_) ? h2s[f - FF1_]
                    : (f == 512)     ? scos
                                     : sdm[f - 513];
            acc = fmaf(w2[r * F2_ + f], v, acc);
        }
        acc = warp_sum(acc);
        if (lane == 0) {
            float z = acc + b2[r];
            float sc = 1.f / (1.f + expf(-z));
            float tgt = 0.f;
            for (int k = 0; k < P_; k++)
                if (ti == rs[b * P_ + k] && tj == re[b * P_ + k] && rq[b * P_ + k] == r)
                    tgt = 1.f;
            float lp = fmaxf(logf(sc), -100.f);
            float l1 = fmaxf(log1pf(-sc), -100.f);
            sbce[r] = -(tgt * lp + (1.f - tgt) * l1);
        }
    }
    __syncthreads();
    if (tid == 0) {
        float s = 0.f;
        for (int r = 0; r < R_; r++) s += sbce[r];
        g_bce[bp] = s * (1.f / R_);
    }
}

__global__ __launch_bounds__(256) void final_red(float* __restrict__ out) {
    const int tid = threadIdx.x, lane = tid & 31, w = tid >> 5;
    float s = 0.f;
    for (int idx = tid; idx < TP_; idx += 256) s += g_bce[idx];
    s = warp_sum(s);
    __shared__ float ws[8];
    if (lane == 0) ws[w] = s;
    __syncthreads();
    if (tid == 0) {
        float t = 0.f;
        for (int k = 0; k < 8; k++) t += ws[k];
        out[0] = t;
    }
}

// ---------------------------------------------------------------------------
// Launch
// ---------------------------------------------------------------------------
extern "C" void kernel_launch(void* const* d_in, const int* in_sizes, int n_in,
                              void* d_out, int out_size)
{
    const float* sh   = (const float*)d_in[0];
    const float* ner  = (const float*)d_in[1];
    const int*   rs   = (const int*)  d_in[2];
    const int*   re   = (const int*)  d_in[3];
    const int*   rq   = (const int*)  d_in[4];
    const float* wqkv = (const float*)d_in[5];
    const float* bqkv = (const float*)d_in[6];
    const float* wo   = (const float*)d_in[7];
    const float* bo   = (const float*)d_in[8];
    const float* g1   = (const float*)d_in[9];
    const float* b1   = (const float*)d_in[10];
    const float* g2   = (const float*)d_in[11];
    const float* b2ln = (const float*)d_in[12];
    const float* w1   = (const float*)d_in[13];
    const float* bf1  = (const float*)d_in[14];
    const float* w2f  = (const float*)d_in[15];
    const float* bf2  = (const float*)d_in[16];
    const float* wr1  = (const float*)d_in[17];
    const float* br1  = (const float*)d_in[18];
    const float* wr2  = (const float*)d_in[19];
    const float* br2  = (const float*)d_in[20];
    const float* Mfull= (const float*)d_in[21];

    // Raise dynamic-smem cap for flash_attn (idempotent; non-allocating)
    cudaFuncSetAttribute(flash_attn, cudaFuncAttributeMaxDynamicSharedMemorySize, FA_SMEM_);

    float *px, *pqkv, *patt, *py, *ph;
    cudaGetSymbolAddress((void**)&px,   g_x);
    cudaGetSymbolAddress((void**)&pqkv, g_qkv);
    cudaGetSymbolAddress((void**)&patt, g_att);
    cudaGetSymbolAddress((void**)&py,   g_y);
    cudaGetSymbolAddress((void**)&ph,   g_h);

    for (int l = 0; l < 2; l++) {
        const float* xin = (l == 0) ? sh : px;   // layer 0 reads the input directly
        sgemm_bias<false><<<dim3(QKV_ / 128, NT_ / 128), 256>>>(
            xin, wqkv + (size_t)l * QKV_ * E_, bqkv + l * QKV_, pqkv, NT_, QKV_, E_);
        flash_attn<<<dim3(T_ / 64, NH_, B_), 256, FA_SMEM_>>>(pqkv, patt);
        sgemm_bias<false><<<dim3(E_ / 128, NT_ / 128), 256>>>(
            patt, wo + (size_t)l * E_ * E_, bo + l * E_, py, NT_, E_, E_);
        add_ln<<<NT_, 128>>>(xin, py, g1 + l * E_, b1 + l * E_, px);
        sgemm_bias<true><<<dim3(E_ / 128, NT_ / 128), 256>>>(
            px, w1 + (size_t)l * E_ * E_, bf1 + l * E_, ph, NT_, E_, E_);
        sgemm_bias<false><<<dim3(E_ / 128, NT_ / 128), 256>>>(
            ph, w2f + (size_t)l * E_ * E_, bf2 + l * E_, py, NT_, E_, E_);
        add_ln<<<NT_, 128>>>(px, py, g2 + l * E_, b2ln + l * E_, px);
    }

    bn_part<<<128, 256>>>(px);
    bn_final<<<2, 256>>>();
    gather_emb<<<dim3(NP_, B_), D_>>>(sh, ner, rs, re, px);
    mdiag_k<<<R_, D_>>>(Mfull);
    rel_h<<<B_ * NP_, 256>>>(wr1, br1);
    pair_k<<<TP_, 256>>>(rs, re, rq, wr2, br2);
    final_red<<<1, 256>>>((float*)d_out);
}

// round 4
// speedup vs baseline: 1.4281x; 1.4281x over previous
#include <cuda_runtime.h>
#include <math.h>
#include <stdint.h>

// ---------------------------------------------------------------------------
// Problem constants
// ---------------------------------------------------------------------------
namespace {
constexpr int B_   = 8;
constexpr int T_   = 1024;
constexpr int E_   = 512;
constexpr int NH_  = 8;
constexpr int HD_  = 64;
constexpr int NT_  = B_ * T_;          // 8192 tokens
constexpr int QKV_ = 3 * E_;           // 1536
constexpr int LBL_ = 64;
constexpr int D_   = E_ + LBL_;        // 576
constexpr int R_   = 16;
constexpr int FF1_ = 256;
constexpr int P_   = 12;
constexpr int NP_  = 24;               // 2P tokens gathered per batch
constexpr int NPAIR_ = 276;            // C(24,2)
constexpr int TP_  = B_ * NPAIR_;      // 2208 pairs
constexpr int F2_  = 2 * FF1_ + 1 + R_; // 529
constexpr float EPS_ = 1e-5f;
constexpr int FA_SMEM_ = 3 * 64 * 68 * (int)sizeof(float);  // 52224 bytes
}

// ---------------------------------------------------------------------------
// Scratch (device globals — no allocation allowed)
// ---------------------------------------------------------------------------
__device__ float g_x  [NT_ * E_];
__device__ float g_qkv[NT_ * QKV_];
__device__ float g_att[NT_ * E_];
__device__ float g_y  [NT_ * E_];
__device__ float g_h  [NT_ * E_];
__device__ float g_bps[128 * E_];
__device__ float g_bpq[128 * E_];
__device__ float g_bsum[E_];
__device__ float g_bsq [E_];
__device__ float g_emb[B_ * NP_ * D_];
__device__ float g_H  [B_ * NP_ * FF1_];
__device__ float g_nrm[B_ * NP_];
__device__ float g_mdiag[R_ * D_];
__device__ float g_bce[TP_];

// ---------------------------------------------------------------------------
// Helpers
// ---------------------------------------------------------------------------
__device__ __forceinline__ float warp_sum(float v) {
#pragma unroll
    for (int off = 16; off; off >>= 1)
        v += __shfl_xor_sync(0xffffffffu, v, off);
    return v;
}

// FMA-pipe exp (no MUFU): exp(x) = 2^(x*log2e), magic-number rint + poly.
// Valid for x <= 0 (all uses here); clamps below -126*ln2.
__device__ __forceinline__ float fast_exp(float x) {
    float t = fmaxf(x * 1.4426950408889634f, -126.0f);
    float z = t + 12582912.0f;              // 1.5*2^23: rint(t) in mantissa
    int   n = __float_as_int(z);            // low bits encode rint(t)
    float r = z - 12582912.0f;              // rint(t)
    float f = t - r;                        // [-0.5, 0.5]
    float p =        1.5353369e-4f;
    p = fmaf(p, f, 1.3398874e-3f);
    p = fmaf(p, f, 9.6184374e-3f);
    p = fmaf(p, f, 5.5503325e-2f);
    p = fmaf(p, f, 2.4022648e-1f);
    p = fmaf(p, f, 6.9314720e-1f);
    p = fmaf(p, f, 1.0f);
    // scale = 2^rint(t):  bits = (rint(t)+127) << 23
    float s = __int_as_float((n - (0x4B400000 - 127)) << 23);
    return p * s;
}

__device__ __forceinline__ uint32_t f2tf(float f) {
    uint32_t u;
    asm("cvt.rna.tf32.f32 %0, %1;" : "=r"(u) : "f"(f));
    return u;
}

__device__ __forceinline__ void mma_tf32(float c[4],
    uint32_t a0, uint32_t a1, uint32_t a2, uint32_t a3,
    uint32_t b0, uint32_t b1)
{
    asm volatile(
        "mma.sync.aligned.m16n8k8.row.col.f32.tf32.tf32.f32 "
        "{%0,%1,%2,%3}, {%4,%5,%6,%7}, {%8,%9}, {%0,%1,%2,%3};"
        : "+f"(c[0]), "+f"(c[1]), "+f"(c[2]), "+f"(c[3])
        : "r"(a0), "r"(a1), "r"(a2), "r"(a3), "r"(b0), "r"(b1));
}

// ---------------------------------------------------------------------------
// TF32 tensor-core GEMM: C[M,N] = A[M,K] * B[N,K]^T + bias (optional ReLU).
// Block 128x128 (256 thr, 8 warps 2x4), warp tile 64x32, BK=16, double-buffered.
// smem pitch 20 words -> conflict-free fragment loads.
// M%128==0, N%128==0, K%16==0 (all hold here).
// ---------------------------------------------------------------------------
__device__ __forceinline__ void mma_chunk(
    const uint32_t* __restrict__ As, const uint32_t* __restrict__ Bs,
    float c[4][4][4], int wm, int wn, int lane)
{
#pragma unroll
    for (int ks = 0; ks < 2; ks++) {
        const int kc = ks * 8 + (lane & 3);
        uint32_t af[4][4];
        const int ar = wm * 64 + (lane >> 2);
#pragma unroll
        for (int mt = 0; mt < 4; mt++) {
            const uint32_t* p = As + (ar + mt * 16) * 20 + kc;
            af[mt][0] = p[0];
            af[mt][1] = p[8 * 20];
            af[mt][2] = p[4];
            af[mt][3] = p[8 * 20 + 4];
        }
        const int br = wn * 32 + (lane >> 2);
#pragma unroll
        for (int nt = 0; nt < 4; nt++) {
            const uint32_t* q = Bs + (br + nt * 8) * 20 + kc;
            uint32_t b0 = q[0], b1 = q[4];
#pragma unroll
            for (int mt = 0; mt < 4; mt++)
                mma_tf32(c[mt][nt], af[mt][0], af[mt][1], af[mt][2], af[mt][3], b0, b1);
        }
    }
}

__device__ __forceinline__ void st8_tf(uint32_t* p, float4 a, float4 b) {
    p[0] = f2tf(a.x); p[1] = f2tf(a.y); p[2] = f2tf(a.z); p[3] = f2tf(a.w);
    p[4] = f2tf(b.x); p[5] = f2tf(b.y); p[6] = f2tf(b.z); p[7] = f2tf(b.w);
}

template <bool RELU>
__global__ __launch_bounds__(256) void gemm_tf32(
    const float* __restrict__ A, const float* __restrict__ Bm,
    const float* __restrict__ bias, float* __restrict__ C,
    int M, int N, int K)
{
    __shared__ uint32_t As[2][128 * 20];
    __shared__ uint32_t Bs[2][128 * 20];

    const int tid = threadIdx.x;
    const int lane = tid & 31, warp = tid >> 5;
    const int wm = warp >> 2;       // 0..1
    const int wn = warp & 3;        // 0..3
    const int bm = blockIdx.y << 7, bn = blockIdx.x << 7;

    const int lrow = tid >> 1;            // 0..127
    const int lq   = (tid & 1) << 3;      // 0 or 8
    const float* Ap = A  + (size_t)(bm + lrow) * K + lq;
    const float* Bp = Bm + (size_t)(bn + lrow) * K + lq;
    const int sb = lrow * 20 + lq;

    float c[4][4][4];
#pragma unroll
    for (int mt = 0; mt < 4; mt++)
#pragma unroll
        for (int nt = 0; nt < 4; nt++)
#pragma unroll
            for (int r = 0; r < 4; r++) c[mt][nt][r] = 0.f;

    // prologue: chunk 0
    float4 pa0 = *(const float4*)(Ap);
    float4 pa1 = *(const float4*)(Ap + 4);
    float4 pb0 = *(const float4*)(Bp);
    float4 pb1 = *(const float4*)(Bp + 4);
    st8_tf(As[0] + sb, pa0, pa1);
    st8_tf(Bs[0] + sb, pb0, pb1);
    __syncthreads();

    int cur = 0;
    for (int k0 = 16; k0 < K; k0 += 16) {
        pa0 = *(const float4*)(Ap + k0);
        pa1 = *(const float4*)(Ap + k0 + 4);
        pb0 = *(const float4*)(Bp + k0);
        pb1 = *(const float4*)(Bp + k0 + 4);
        mma_chunk(As[cur], Bs[cur], c, wm, wn, lane);
        st8_tf(As[cur ^ 1] + sb, pa0, pa1);
        st8_tf(Bs[cur ^ 1] + sb, pb0, pb1);
        __syncthreads();
        cur ^= 1;
    }
    mma_chunk(As[cur], Bs[cur], c, wm, wn, lane);

    // epilogue: bias (+ReLU), write float2 pairs
#pragma unroll
    for (int nt = 0; nt < 4; nt++) {
        const int col = bn + wn * 32 + nt * 8 + ((lane & 3) << 1);
        float2 bv = *(const float2*)&bias[col];
#pragma unroll
        for (int mt = 0; mt < 4; mt++) {
            int row0 = bm + wm * 64 + mt * 16 + (lane >> 2);
            float2 v0 = make_float2(c[mt][nt][0] + bv.x, c[mt][nt][1] + bv.y);
            float2 v1 = make_float2(c[mt][nt][2] + bv.x, c[mt][nt][3] + bv.y);
            if (RELU) {
                v0.x = fmaxf(v0.x, 0.f); v0.y = fmaxf(v0.y, 0.f);
                v1.x = fmaxf(v1.x, 0.f); v1.y = fmaxf(v1.y, 0.f);
            }
            *(float2*)&C[(size_t)row0 * N + col]       = v0;
            *(float2*)&C[(size_t)(row0 + 8) * N + col] = v1;
        }
    }
}

// ---------------------------------------------------------------------------
// Flash attention, fp32 FMA + polynomial exp (no MUFU). grid (T/64, NH, B).
// Dynamic smem: Qs[64][68] | KP[64][68] | Vs[64][68]  (52224 B).
// ---------------------------------------------------------------------------
__global__ __launch_bounds__(256) void flash_attn(const float* __restrict__ qkv,
                                                  float* __restrict__ out)
{
    extern __shared__ float fa_smem[];
    float (*Qs)[68] = (float(*)[68])fa_smem;
    float (*KP)[68] = (float(*)[68])(fa_smem + 64*68);
    float (*Vs)[68] = (float(*)[68])(fa_smem + 2*64*68);
    const int tid = threadIdx.x;
    const int tx = tid & 15, ty = tid >> 4;
    const int q0 = blockIdx.x << 6;
    const int h  = blockIdx.y;
    const int b  = blockIdx.z;
    const float* base = qkv + (size_t)b * T_ * QKV_;

#pragma unroll
    for (int it = 0; it < 4; it++) {
        int idx = tid + (it << 8);
        int r = idx >> 4, c = (idx & 15) << 2;
        float4 v = *(const float4*)(base + (size_t)(q0 + r) * QKV_ + h * HD_ + c);
        *(float4*)&Qs[r][c] = v;
    }

    float m[4], l[4], o[4][4];
#pragma unroll
    for (int i = 0; i < 4; i++) {
        m[i] = -1e30f; l[i] = 0.f;
#pragma unroll
        for (int j = 0; j < 4; j++) o[i][j] = 0.f;
    }

    for (int kt = 0; kt < 16; kt++) {
        const int k0 = kt << 6;
        __syncthreads();
#pragma unroll
        for (int it = 0; it < 4; it++) {
            int idx = tid + (it << 8);
            int r = idx >> 4, c = (idx & 15) << 2;
            const float* kr = base + (size_t)(k0 + r) * QKV_ + E_ + h * HD_ + c;
            float4 kv = *(const float4*)kr;
            KP[c+0][r] = kv.x; KP[c+1][r] = kv.y; KP[c+2][r] = kv.z; KP[c+3][r] = kv.w;
            float4 vv = *(const float4*)(kr + E_);
            *(float4*)&Vs[r][c] = vv;
        }
        __syncthreads();

        float s[4][4];
#pragma unroll
        for (int i = 0; i < 4; i++)
#pragma unroll
            for (int j = 0; j < 4; j++) s[i][j] = 0.f;

#pragma unroll 8
        for (int d = 0; d < 64; d++) {
            float a0 = Qs[(ty<<2)+0][d];
            float a1 = Qs[(ty<<2)+1][d];
            float a2 = Qs[(ty<<2)+2][d];
            float a3 = Qs[(ty<<2)+3][d];
            float4 bb = *(const float4*)&KP[d][tx << 2];
            s[0][0]=fmaf(a0,bb.x,s[0][0]); s[0][1]=fmaf(a0,bb.y,s[0][1]); s[0][2]=fmaf(a0,bb.z,s[0][2]); s[0][3]=fmaf(a0,bb.w,s[0][3]);
            s[1][0]=fmaf(a1,bb.x,s[1][0]); s[1][1]=fmaf(a1,bb.y,s[1][1]); s[1][2]=fmaf(a1,bb.z,s[1][2]); s[1][3]=fmaf(a1,bb.w,s[1][3]);
            s[2][0]=fmaf(a2,bb.x,s[2][0]); s[2][1]=fmaf(a2,bb.y,s[2][1]); s[2][2]=fmaf(a2,bb.z,s[2][2]); s[2][3]=fmaf(a2,bb.w,s[2][3]);
            s[3][0]=fmaf(a3,bb.x,s[3][0]); s[3][1]=fmaf(a3,bb.y,s[3][1]); s[3][2]=fmaf(a3,bb.z,s[3][2]); s[3][3]=fmaf(a3,bb.w,s[3][3]);
        }

#pragma unroll
        for (int i = 0; i < 4; i++) {
            float rm = -1e30f;
#pragma unroll
            for (int j = 0; j < 4; j++) { s[i][j] *= 0.125f; rm = fmaxf(rm, s[i][j]); }
#pragma unroll
            for (int off = 8; off; off >>= 1)
                rm = fmaxf(rm, __shfl_xor_sync(0xffffffffu, rm, off, 16));
            float mn = fmaxf(m[i], rm);
            float rs = 0.f;
#pragma unroll
            for (int j = 0; j < 4; j++) { s[i][j] = fast_exp(s[i][j] - mn); rs += s[i][j]; }
#pragma unroll
            for (int off = 8; off; off >>= 1)
                rs += __shfl_xor_sync(0xffffffffu, rs, off, 16);
            float corr = fast_exp(m[i] - mn);
            l[i] = l[i] * corr + rs;
            m[i] = mn;
#pragma unroll
            for (int j = 0; j < 4; j++) o[i][j] *= corr;
        }

        __syncthreads();
#pragma unroll
        for (int i = 0; i < 4; i++)
#pragma unroll
            for (int j = 0; j < 4; j++)
                KP[(ty<<2)+i][(tx<<2)+j] = s[i][j];
        __syncthreads();

#pragma unroll 8
        for (int d = 0; d < 64; d++) {
            float p0 = KP[(ty<<2)+0][d];
            float p1 = KP[(ty<<2)+1][d];
            float p2 = KP[(ty<<2)+2][d];
            float p3 = KP[(ty<<2)+3][d];
            float4 vv = *(const float4*)&Vs[d][tx << 2];
            o[0][0]=fmaf(p0,vv.x,o[0][0]); o[0][1]=fmaf(p0,vv.y,o[0][1]); o[0][2]=fmaf(p0,vv.z,o[0][2]); o[0][3]=fmaf(p0,vv.w,o[0][3]);
            o[1][0]=fmaf(p1,vv.x,o[1][0]); o[1][1]=fmaf(p1,vv.y,o[1][1]); o[1][2]=fmaf(p1,vv.z,o[1][2]); o[1][3]=fmaf(p1,vv.w,o[1][3]);
            o[2][0]=fmaf(p2,vv.x,o[2][0]); o[2][1]=fmaf(p2,vv.y,o[2][1]); o[2][2]=fmaf(p2,vv.z,o[2][2]); o[2][3]=fmaf(p2,vv.w,o[2][3]);
            o[3][0]=fmaf(p3,vv.x,o[3][0]); o[3][1]=fmaf(p3,vv.y,o[3][1]); o[3][2]=fmaf(p3,vv.z,o[3][2]); o[3][3]=fmaf(p3,vv.w,o[3][3]);
        }
    }

#pragma unroll
    for (int i = 0; i < 4; i++) {
        float inv = 1.f / l[i];
        float4 r = make_float4(o[i][0]*inv, o[i][1]*inv, o[i][2]*inv, o[i][3]*inv);
        *(float4*)&out[(size_t)(b * T_ + q0 + (ty<<2) + i) * E_ + h * HD_ + (tx<<2)] = r;
    }
}

// ---------------------------------------------------------------------------
// out = LayerNorm(x + y) * g + b   (one block per row, 128 threads)
// ---------------------------------------------------------------------------
__global__ __launch_bounds__(128) void add_ln(
    const float* __restrict__ x, const float* __restrict__ y,
    const float* __restrict__ g, const float* __restrict__ be,
    float* __restrict__ outp)
{
    const int row = blockIdx.x, tid = threadIdx.x;
    const int c4 = tid << 2;
    float4 xv = *(const float4*)&x[(size_t)row * E_ + c4];
    float4 yv = *(const float4*)&y[(size_t)row * E_ + c4];
    float v[4] = {xv.x + yv.x, xv.y + yv.y, xv.z + yv.z, xv.w + yv.w};
    float s = 0.f, q = 0.f;
#pragma unroll
    for (int c = 0; c < 4; c++) { s += v[c]; q = fmaf(v[c], v[c], q); }
    s = warp_sum(s); q = warp_sum(q);
    __shared__ float ws[4], wq[4];
    const int lane = tid & 31, w = tid >> 5;
    if (lane == 0) { ws[w] = s; wq[w] = q; }
    __syncthreads();
    s = ws[0] + ws[1] + ws[2] + ws[3];
    q = wq[0] + wq[1] + wq[2] + wq[3];
    const float mu   = s * (1.f / E_);
    const float var  = q * (1.f / E_) - mu * mu;
    const float rstd = rsqrtf(var + EPS_);
    float4 gv = *(const float4*)&g[c4];
    float4 bv = *(const float4*)&be[c4];
    float4 ov;
    ov.x = (v[0] - mu) * rstd * gv.x + bv.x;
    ov.y = (v[1] - mu) * rstd * gv.y + bv.y;
    ov.z = (v[2] - mu) * rstd * gv.z + bv.z;
    ov.w = (v[3] - mu) * rstd * gv.w + bv.w;
    *(float4*)&outp[(size_t)row * E_ + c4] = ov;
}

// ---------------------------------------------------------------------------
// Batch-norm stats over all 8192 rows, two deterministic stages
// ---------------------------------------------------------------------------
__global__ __launch_bounds__(256) void bn_part(const float* __restrict__ x) {
    const int blk = blockIdx.x, tid = threadIdx.x;
    float s0 = 0.f, q0 = 0.f, s1 = 0.f, q1 = 0.f;
    const size_t rb = (size_t)blk * 64 * E_;
    for (int r = 0; r < 64; r++) {
        float a = x[rb + (size_t)r * E_ + tid];
        float c = x[rb + (size_t)r * E_ + 256 + tid];
        s0 += a; q0 = fmaf(a, a, q0);
        s1 += c; q1 = fmaf(c, c, q1);
    }
    g_bps[blk * E_ + tid] = s0;        g_bpq[blk * E_ + tid] = q0;
    g_bps[blk * E_ + 256 + tid] = s1;  g_bpq[blk * E_ + 256 + tid] = q1;
}

__global__ void bn_final() {
    const int c = blockIdx.x * blockDim.x + threadIdx.x;   // 512 threads total
    float s = 0.f, q = 0.f;
    for (int p = 0; p < 128; p++) { s += g_bps[p * E_ + c]; q += g_bpq[p * E_ + c]; }
    g_bsum[c] = s; g_bsq[c] = q;
}

// ---------------------------------------------------------------------------
// Gather rep at the 24 tokens per batch: emb = [shared + bn(out), ner]
// ---------------------------------------------------------------------------
__global__ void gather_emb(const float* __restrict__ sh, const float* __restrict__ ner,
                           const int* __restrict__ rs, const int* __restrict__ re,
                           const float* __restrict__ xw)
{
    const int j = blockIdx.x, b = blockIdx.y, d = threadIdx.x;
    const int t = (j < P_) ? rs[b * P_ + j] : re[b * P_ + j - P_];
    float v;
    if (d < E_) {
        float mu   = g_bsum[d] * (1.f / NT_);
        float var  = g_bsq[d] * (1.f / NT_) - mu * mu;
        float rstd = rsqrtf(var + EPS_);
        size_t off = ((size_t)b * T_ + t) * E_ + d;
        v = sh[off] + (xw[off] - mu) * rstd;
    } else {
        v = ner[((size_t)b * T_ + t) * LBL_ + (d - E_)];
    }
    g_emb[(b * NP_ + j) * D_ + d] = v;
}

// M is diag-constructed: extract diagonal once (off-diagonals are exactly 0)
__global__ void mdiag_k(const float* __restrict__ M) {
    const int r = blockIdx.x, d = threadIdx.x;
    g_mdiag[r * D_ + d] = M[((size_t)r * D_ + d) * D_ + d];
}

// ---------------------------------------------------------------------------
// H[b,j] = relu(W1 @ emb + b1), plus its norm. grid 192, 256 threads (8 warps)
// ---------------------------------------------------------------------------
__global__ __launch_bounds__(256) void rel_h(const float* __restrict__ w1,
                                             const float* __restrict__ b1)
{
    __shared__ float es[D_];
    __shared__ float Hs[FF1_];
    __shared__ float wsum[8];
    const int bj = blockIdx.x, tid = threadIdx.x, lane = tid & 31, w = tid >> 5;
    for (int d = tid; d < D_; d += 256) es[d] = g_emb[bj * D_ + d];
    __syncthreads();
    for (int f = w; f < FF1_; f += 8) {
        float acc = 0.f;
        const float* wr = w1 + (size_t)f * D_;
        for (int d = lane; d < D_; d += 32) acc = fmaf(wr[d], es[d], acc);
        acc = warp_sum(acc);
        if (lane == 0) Hs[f] = fmaxf(acc + b1[f], 0.f);
    }
    __syncthreads();
    float hv = Hs[tid];
    g_H[bj * FF1_ + tid] = hv;
    float q = warp_sum(hv * hv);
    if (lane == 0) wsum[w] = q;
    __syncthreads();
    if (tid == 0) {
        float ss = 0.f;
        for (int k = 0; k < 8; k++) ss += wsum[k];
        g_nrm[bj] = fmaxf(sqrtf(ss), 1e-8f);
    }
}

// ---------------------------------------------------------------------------
// Per-pair scores + BCE. grid 2208, 256 threads (8 warps)
// ---------------------------------------------------------------------------
__global__ __launch_bounds__(256) void pair_k(
    const int* __restrict__ rs, const int* __restrict__ re, const int* __restrict__ rq,
    const float* __restrict__ w2, const float* __restrict__ b2)
{
    const int bp = blockIdx.x;
    const int b = bp / NPAIR_, p = bp % NPAIR_;
    int i = 0, rem = p, cnt = NP_ - 1;
    while (rem >= cnt) { rem -= cnt; i++; cnt--; }
    const int j = i + 1 + rem;

    __shared__ float e1[D_], e2[D_], h1s[FF1_], h2s[FF1_];
    __shared__ float sdm[R_], sred[8], sbce[R_];
    __shared__ float scos;
    const int tid = threadIdx.x, lane = tid & 31, w = tid >> 5;
    const int bi = b * NP_ + i, bj = b * NP_ + j;

    for (int d = tid; d < D_; d += 256) { e1[d] = g_emb[bi * D_ + d]; e2[d] = g_emb[bj * D_ + d]; }
    h1s[tid] = g_H[bi * FF1_ + tid];
    h2s[tid] = g_H[bj * FF1_ + tid];
    __syncthreads();

    float pp = warp_sum(h1s[tid] * h2s[tid]);
    if (lane == 0) sred[w] = pp;
    __syncthreads();
    if (tid == 0) {
        float hh = 0.f;
        for (int k = 0; k < 8; k++) hh += sred[k];
        scos = hh / (g_nrm[bi] * g_nrm[bj]);
    }
    for (int r = w; r < R_; r += 8) {
        float acc = 0.f;
        for (int d = lane; d < D_; d += 32)
            acc = fmaf(g_mdiag[r * D_ + d], e1[d] * e2[d], acc);
        acc = warp_sum(acc);
        if (lane == 0) sdm[r] = acc;
    }
    __syncthreads();

    const int ti = (i < P_) ? rs[b * P_ + i] : re[b * P_ + i - P_];
    const int tj = (j < P_) ? rs[b * P_ + j] : re[b * P_ + j - P_];

    for (int r = w; r < R_; r += 8) {
        float acc = 0.f;
        for (int f = lane; f < F2_; f += 32) {
            float v = (f < FF1_)     ? h1s[f]
                    : (f < 2 * FF1_) ? h2s[f - FF1_]
                    : (f == 512)     ? scos
                                     : sdm[f - 513];
            acc = fmaf(w2[r * F2_ + f], v, acc);
        }
        acc = warp_sum(acc);
        if (lane == 0) {
            float z = acc + b2[r];
            float sc = 1.f / (1.f + expf(-z));
            float tgt = 0.f;
            for (int k = 0; k < P_; k++)
                if (ti == rs[b * P_ + k] && tj == re[b * P_ + k] && rq[b * P_ + k] == r)
                    tgt = 1.f;
            float lp = fmaxf(logf(sc), -100.f);
            float l1 = fmaxf(log1pf(-sc), -100.f);
            sbce[r] = -(tgt * lp + (1.f - tgt) * l1);
        }
    }
    __syncthreads();
    if (tid == 0) {
        float s = 0.f;
        for (int r = 0; r < R_; r++) s += sbce[r];
        g_bce[bp] = s * (1.f / R_);
    }
}

__global__ __launch_bounds__(256) void final_red(float* __restrict__ out) {
    const int tid = threadIdx.x, lane = tid & 31, w = tid >> 5;
    float s = 0.f;
    for (int idx = tid; idx < TP_; idx += 256) s += g_bce[idx];
    s = warp_sum(s);
    __shared__ float ws[8];
    if (lane == 0) ws[w] = s;
    __syncthreads();
    if (tid == 0) {
        float t = 0.f;
        for (int k = 0; k < 8; k++) t += ws[k];
        out[0] = t;
    }
}

// ---------------------------------------------------------------------------
// Launch
// ---------------------------------------------------------------------------
extern "C" void kernel_launch(void* const* d_in, const int* in_sizes, int n_in,
                              void* d_out, int out_size)
{
    const float* sh   = (const float*)d_in[0];
    const float* ner  = (const float*)d_in[1];
    const int*   rs   = (const int*)  d_in[2];
    const int*   re   = (const int*)  d_in[3];
    const int*   rq   = (const int*)  d_in[4];
    const float* wqkv = (const float*)d_in[5];
    const float* bqkv = (const float*)d_in[6];
    const float* wo   = (const float*)d_in[7];
    const float* bo   = (const float*)d_in[8];
    const float* g1   = (const float*)d_in[9];
    const float* b1   = (const float*)d_in[10];
    const float* g2   = (const float*)d_in[11];
    const float* b2ln = (const float*)d_in[12];
    const float* w1   = (const float*)d_in[13];
    const float* bf1  = (const float*)d_in[14];
    const float* w2f  = (const float*)d_in[15];
    const float* bf2  = (const float*)d_in[16];
    const float* wr1  = (const float*)d_in[17];
    const float* br1  = (const float*)d_in[18];
    const float* wr2  = (const float*)d_in[19];
    const float* br2  = (const float*)d_in[20];
    const float* Mfull= (const float*)d_in[21];

    cudaFuncSetAttribute(flash_attn, cudaFuncAttributeMaxDynamicSharedMemorySize, FA_SMEM_);

    float *px, *pqkv, *patt, *py, *ph;
    cudaGetSymbolAddress((void**)&px,   g_x);
    cudaGetSymbolAddress((void**)&pqkv, g_qkv);
    cudaGetSymbolAddress((void**)&patt, g_att);
    cudaGetSymbolAddress((void**)&py,   g_y);
    cudaGetSymbolAddress((void**)&ph,   g_h);

    for (int l = 0; l < 2; l++) {
        const float* xin = (l == 0) ? sh : px;
        gemm_tf32<false><<<dim3(QKV_ / 128, NT_ / 128), 256>>>(
            xin, wqkv + (size_t)l * QKV_ * E_, bqkv + l * QKV_, pqkv, NT_, QKV_, E_);
        flash_attn<<<dim3(T_ / 64, NH_, B_), 256, FA_SMEM_>>>(pqkv, patt);
        gemm_tf32<false><<<dim3(E_ / 128, NT_ / 128), 256>>>(
            patt, wo + (size_t)l * E_ * E_, bo + l * E_, py, NT_, E_, E_);
        add_ln<<<NT_, 128>>>(xin, py, g1 + l * E_, b1 + l * E_, px);
        gemm_tf32<true><<<dim3(E_ / 128, NT_ / 128), 256>>>(
            px, w1 + (size_t)l * E_ * E_, bf1 + l * E_, ph, NT_, E_, E_);
        gemm_tf32<false><<<dim3(E_ / 128, NT_ / 128), 256>>>(
            ph, w2f + (size_t)l * E_ * E_, bf2 + l * E_, py, NT_, E_, E_);
        add_ln<<<NT_, 128>>>(px, py, g2 + l * E_, b2ln + l * E_, px);
    }

    bn_part<<<128, 256>>>(px);
    bn_final<<<2, 256>>>();
    gather_emb<<<dim3(NP_, B_), D_>>>(sh, ner, rs, re, px);
    mdiag_k<<<R_, D_>>>(Mfull);
    rel_h<<<B_ * NP_, 256>>>(wr1, br1);
    pair_k<<<TP_, 256>>>(rs, re, rq, wr2, br2);
    final_red<<<1, 256>>>((float*)d_out);
}

// round 5
// speedup vs baseline: 2.1081x; 1.4761x over previous
#include <cuda_runtime.h>
#include <math.h>
#include <stdint.h>

// ---------------------------------------------------------------------------
// Problem constants
// ---------------------------------------------------------------------------
namespace {
constexpr int B_   = 8;
constexpr int T_   = 1024;
constexpr int E_   = 512;
constexpr int NH_  = 8;
constexpr int HD_  = 64;
constexpr int NT_  = B_ * T_;          // 8192 tokens
constexpr int QKV_ = 3 * E_;           // 1536
constexpr int LBL_ = 64;
constexpr int D_   = E_ + LBL_;        // 576
constexpr int R_   = 16;
constexpr int FF1_ = 256;
constexpr int P_   = 12;
constexpr int NP_  = 24;               // 2P tokens gathered per batch
constexpr int NPAIR_ = 276;            // C(24,2)
constexpr int TP_  = B_ * NPAIR_;      // 2208 pairs
constexpr int F2_  = 2 * FF1_ + 1 + R_; // 529
constexpr float EPS_ = 1e-5f;
// flash-attn TC smem: Ks[64][68] + Vst[64][68] + Ps[128][68]  (uint32 words)
constexpr int FA_WORDS_ = (64 + 64 + 128) * 68;
constexpr int FA_SMEM_  = FA_WORDS_ * 4;   // 69632 bytes
}

// ---------------------------------------------------------------------------
// Scratch (device globals — no allocation allowed)
// ---------------------------------------------------------------------------
__device__ float g_x  [NT_ * E_];
__device__ float g_qkv[NT_ * QKV_];
__device__ float g_att[NT_ * E_];
__device__ float g_y  [NT_ * E_];
__device__ float g_h  [NT_ * E_];
__device__ float g_bps[128 * E_];
__device__ float g_bpq[128 * E_];
__device__ float g_bsum[E_];
__device__ float g_bsq [E_];
__device__ float g_emb[B_ * NP_ * D_];
__device__ float g_H  [B_ * NP_ * FF1_];
__device__ float g_nrm[B_ * NP_];
__device__ float g_mdiag[R_ * D_];
__device__ float g_bce[TP_];

// ---------------------------------------------------------------------------
// Helpers
// ---------------------------------------------------------------------------
__device__ __forceinline__ float warp_sum(float v) {
#pragma unroll
    for (int off = 16; off; off >>= 1)
        v += __shfl_xor_sync(0xffffffffu, v, off);
    return v;
}

// FMA-pipe exp (no MUFU): exp(x) = 2^(x*log2e). Valid for x <= 0.
__device__ __forceinline__ float fast_exp(float x) {
    float t = fmaxf(x * 1.4426950408889634f, -126.0f);
    float z = t + 12582912.0f;
    int   n = __float_as_int(z);
    float r = z - 12582912.0f;
    float f = t - r;
    float p =        1.5353369e-4f;
    p = fmaf(p, f, 1.3398874e-3f);
    p = fmaf(p, f, 9.6184374e-3f);
    p = fmaf(p, f, 5.5503325e-2f);
    p = fmaf(p, f, 2.4022648e-1f);
    p = fmaf(p, f, 6.9314720e-1f);
    p = fmaf(p, f, 1.0f);
    float s = __int_as_float((n - (0x4B400000 - 127)) << 23);
    return p * s;
}

__device__ __forceinline__ uint32_t f2tf(float f) {
    uint32_t u;
    asm("cvt.rna.tf32.f32 %0, %1;" : "=r"(u) : "f"(f));
    return u;
}

__device__ __forceinline__ void mma_tf32(float c[4],
    uint32_t a0, uint32_t a1, uint32_t a2, uint32_t a3,
    uint32_t b0, uint32_t b1)
{
    asm volatile(
        "mma.sync.aligned.m16n8k8.row.col.f32.tf32.tf32.f32 "
        "{%0,%1,%2,%3}, {%4,%5,%6,%7}, {%8,%9}, {%0,%1,%2,%3};"
        : "+f"(c[0]), "+f"(c[1]), "+f"(c[2]), "+f"(c[3])
        : "r"(a0), "r"(a1), "r"(a2), "r"(a3), "r"(b0), "r"(b1));
}

// ---------------------------------------------------------------------------
// TF32 tensor-core GEMM: C[M,N] = A[M,K] * B[N,K]^T + bias (optional ReLU).
// Block 128x128 (256 thr, 8 warps 2x4), warp tile 64x32, BK=16, double-buffered.
// ---------------------------------------------------------------------------
__device__ __forceinline__ void mma_chunk(
    const uint32_t* __restrict__ As, const uint32_t* __restrict__ Bs,
    float c[4][4][4], int wm, int wn, int lane)
{
#pragma unroll
    for (int ks = 0; ks < 2; ks++) {
        const int kc = ks * 8 + (lane & 3);
        uint32_t af[4][4];
        const int ar = wm * 64 + (lane >> 2);
#pragma unroll
        for (int mt = 0; mt < 4; mt++) {
            const uint32_t* p = As + (ar + mt * 16) * 20 + kc;
            af[mt][0] = p[0];
            af[mt][1] = p[8 * 20];
            af[mt][2] = p[4];
            af[mt][3] = p[8 * 20 + 4];
        }
        const int br = wn * 32 + (lane >> 2);
#pragma unroll
        for (int nt = 0; nt < 4; nt++) {
            const uint32_t* q = Bs + (br + nt * 8) * 20 + kc;
            uint32_t b0 = q[0], b1 = q[4];
#pragma unroll
            for (int mt = 0; mt < 4; mt++)
                mma_tf32(c[mt][nt], af[mt][0], af[mt][1], af[mt][2], af[mt][3], b0, b1);
        }
    }
}

__device__ __forceinline__ void st8_tf(uint32_t* p, float4 a, float4 b) {
    p[0] = f2tf(a.x); p[1] = f2tf(a.y); p[2] = f2tf(a.z); p[3] = f2tf(a.w);
    p[4] = f2tf(b.x); p[5] = f2tf(b.y); p[6] = f2tf(b.z); p[7] = f2tf(b.w);
}

template <bool RELU>
__global__ __launch_bounds__(256) void gemm_tf32(
    const float* __restrict__ A, const float* __restrict__ Bm,
    const float* __restrict__ bias, float* __restrict__ C,
    int M, int N, int K)
{
    __shared__ uint32_t As[2][128 * 20];
    __shared__ uint32_t Bs[2][128 * 20];

    const int tid = threadIdx.x;
    const int lane = tid & 31, warp = tid >> 5;
    const int wm = warp >> 2;
    const int wn = warp & 3;
    const int bm = blockIdx.y << 7, bn = blockIdx.x << 7;

    const int lrow = tid >> 1;
    const int lq   = (tid & 1) << 3;
    const float* Ap = A  + (size_t)(bm + lrow) * K + lq;
    const float* Bp = Bm + (size_t)(bn + lrow) * K + lq;
    const int sb = lrow * 20 + lq;

    float c[4][4][4];
#pragma unroll
    for (int mt = 0; mt < 4; mt++)
#pragma unroll
        for (int nt = 0; nt < 4; nt++)
#pragma unroll
            for (int r = 0; r < 4; r++) c[mt][nt][r] = 0.f;

    float4 pa0 = *(const float4*)(Ap);
    float4 pa1 = *(const float4*)(Ap + 4);
    float4 pb0 = *(const float4*)(Bp);
    float4 pb1 = *(const float4*)(Bp + 4);
    st8_tf(As[0] + sb, pa0, pa1);
    st8_tf(Bs[0] + sb, pb0, pb1);
    __syncthreads();

    int cur = 0;
    for (int k0 = 16; k0 < K; k0 += 16) {
        pa0 = *(const float4*)(Ap + k0);
        pa1 = *(const float4*)(Ap + k0 + 4);
        pb0 = *(const float4*)(Bp + k0);
        pb1 = *(const float4*)(Bp + k0 + 4);
        mma_chunk(As[cur], Bs[cur], c, wm, wn, lane);
        st8_tf(As[cur ^ 1] + sb, pa0, pa1);
        st8_tf(Bs[cur ^ 1] + sb, pb0, pb1);
        __syncthreads();
        cur ^= 1;
    }
    mma_chunk(As[cur], Bs[cur], c, wm, wn, lane);

#pragma unroll
    for (int nt = 0; nt < 4; nt++) {
        const int col = bn + wn * 32 + nt * 8 + ((lane & 3) << 1);
        float2 bv = *(const float2*)&bias[col];
#pragma unroll
        for (int mt = 0; mt < 4; mt++) {
            int row0 = bm + wm * 64 + mt * 16 + (lane >> 2);
            float2 v0 = make_float2(c[mt][nt][0] + bv.x, c[mt][nt][1] + bv.y);
            float2 v1 = make_float2(c[mt][nt][2] + bv.x, c[mt][nt][3] + bv.y);
            if (RELU) {
                v0.x = fmaxf(v0.x, 0.f); v0.y = fmaxf(v0.y, 0.f);
                v1.x = fmaxf(v1.x, 0.f); v1.y = fmaxf(v1.y, 0.f);
            }
            *(float2*)&C[(size_t)row0 * N + col]       = v0;
            *(float2*)&C[(size_t)(row0 + 8) * N + col] = v1;
        }
    }
}

// ---------------------------------------------------------------------------
// Tensor-core flash attention (tf32 mma). grid (T/128, NH, B), 256 thr, 8 warps.
// Each warp owns 16 q-rows. KV tile = 64 tokens.
// smem: Ks[64][68] (tf32, [tok][d]) | Vst[64][68] (tf32, [d][tok]) | Ps[128][68].
// Q fragments live in registers for the whole kernel.
// mma m16n8k8 fragment ownership (lane g = lane>>2, q = lane&3):
//   A: a0=(g, q) a1=(g+8, q) a2=(g, q+4) a3=(g+8, q+4)
//   B: b0=(k=q, n=g) b1=(k=q+4, n=g)
//   C: c0=(g, 2q) c1=(g, 2q+1) c2=(g+8, 2q) c3=(g+8, 2q+1)
// ---------------------------------------------------------------------------
__global__ __launch_bounds__(256) void flash_attn_tc(const float* __restrict__ qkv,
                                                     float* __restrict__ out)
{
    extern __shared__ uint32_t fa_sm[];
    uint32_t (*Ks) [68] = (uint32_t(*)[68])fa_sm;
    uint32_t (*Vst)[68] = (uint32_t(*)[68])(fa_sm + 64 * 68);
    uint32_t (*Ps) [68] = (uint32_t(*)[68])(fa_sm + 2 * 64 * 68);

    const int tid  = threadIdx.x;
    const int lane = tid & 31, warp = tid >> 5;
    const int g = lane >> 2, qd = lane & 3;
    const int q0 = blockIdx.x << 7;
    const int h  = blockIdx.y;
    const int b  = blockIdx.z;
    const float* base = qkv + (size_t)b * T_ * QKV_;

    // stage Q tile (128x64) into Ps as tf32, coalesced
#pragma unroll
    for (int it = 0; it < 8; it++) {
        int idx = it * 256 + tid;
        int r = idx >> 4, c = (idx & 15) << 2;
        float4 v = *(const float4*)(base + (size_t)(q0 + r) * QKV_ + h * HD_ + c);
        Ps[r][c+0] = f2tf(v.x); Ps[r][c+1] = f2tf(v.y);
        Ps[r][c+2] = f2tf(v.z); Ps[r][c+3] = f2tf(v.w);
    }
    __syncthreads();

    // Q fragments -> registers (per warp: rows warp*16 .. +15)
    const int ar = warp * 16 + g;   // local A-row (also used for Ps later)
    uint32_t qf[8][4];
#pragma unroll
    for (int kc = 0; kc < 8; kc++) {
        qf[kc][0] = Ps[ar    ][kc * 8 + qd];
        qf[kc][1] = Ps[ar + 8][kc * 8 + qd];
        qf[kc][2] = Ps[ar    ][kc * 8 + qd + 4];
        qf[kc][3] = Ps[ar + 8][kc * 8 + qd + 4];
    }
    // NOTE: from here on, Ps rows [warp*16, warp*16+16) are used ONLY by this warp.

    float m0 = -1e30f, m1 = -1e30f, l0 = 0.f, l1 = 0.f;
    float of[8][4];
#pragma unroll
    for (int n = 0; n < 8; n++)
#pragma unroll
        for (int r = 0; r < 4; r++) of[n][r] = 0.f;

    for (int kt = 0; kt < 16; kt++) {
        const int k0g = kt << 6;
        __syncthreads();   // Ks/Vst reads of previous tile complete
        // load K (natural) and V (transposed) tiles as tf32
#pragma unroll
        for (int it = 0; it < 4; it++) {
            int idx = it * 256 + tid;
            int r = idx >> 4, c = (idx & 15) << 2;
            const float* kr = base + (size_t)(k0g + r) * QKV_ + E_ + h * HD_ + c;
            float4 kv = *(const float4*)kr;
            Ks[r][c+0] = f2tf(kv.x); Ks[r][c+1] = f2tf(kv.y);
            Ks[r][c+2] = f2tf(kv.z); Ks[r][c+3] = f2tf(kv.w);
            float4 vv = *(const float4*)(kr + E_);
            Vst[c+0][r] = f2tf(vv.x); Vst[c+1][r] = f2tf(vv.y);
            Vst[c+2][r] = f2tf(vv.z); Vst[c+3][r] = f2tf(vv.w);
        }
        __syncthreads();

        // S = Q K^T  (16 x 64 per warp)
        float sc[8][4];
#pragma unroll
        for (int n = 0; n < 8; n++)
#pragma unroll
            for (int r = 0; r < 4; r++) sc[n][r] = 0.f;
#pragma unroll
        for (int kc = 0; kc < 8; kc++) {
#pragma unroll
            for (int n = 0; n < 8; n++) {
                uint32_t b0 = Ks[n * 8 + g][kc * 8 + qd];
                uint32_t b1 = Ks[n * 8 + g][kc * 8 + qd + 4];
                mma_tf32(sc[n], qf[kc][0], qf[kc][1], qf[kc][2], qf[kc][3], b0, b1);
            }
        }

        // online softmax on fragments (thread owns rows g, g+8; 2 cols per ntile)
        float rm0 = -1e30f, rm1 = -1e30f;
#pragma unroll
        for (int n = 0; n < 8; n++) {
            sc[n][0] *= 0.125f; sc[n][1] *= 0.125f;
            sc[n][2] *= 0.125f; sc[n][3] *= 0.125f;
            rm0 = fmaxf(rm0, fmaxf(sc[n][0], sc[n][1]));
            rm1 = fmaxf(rm1, fmaxf(sc[n][2], sc[n][3]));
        }
        rm0 = fmaxf(rm0, __shfl_xor_sync(0xffffffffu, rm0, 1));
        rm0 = fmaxf(rm0, __shfl_xor_sync(0xffffffffu, rm0, 2));
        rm1 = fmaxf(rm1, __shfl_xor_sync(0xffffffffu, rm1, 1));
        rm1 = fmaxf(rm1, __shfl_xor_sync(0xffffffffu, rm1, 2));
        const float mn0 = fmaxf(m0, rm0), mn1 = fmaxf(m1, rm1);
        float rs0 = 0.f, rs1 = 0.f;
#pragma unroll
        for (int n = 0; n < 8; n++) {
            sc[n][0] = fast_exp(sc[n][0] - mn0);
            sc[n][1] = fast_exp(sc[n][1] - mn0);
            sc[n][2] = fast_exp(sc[n][2] - mn1);
            sc[n][3] = fast_exp(sc[n][3] - mn1);
            rs0 += sc[n][0] + sc[n][1];
            rs1 += sc[n][2] + sc[n][3];
        }
        rs0 += __shfl_xor_sync(0xffffffffu, rs0, 1);
        rs0 += __shfl_xor_sync(0xffffffffu, rs0, 2);
        rs1 += __shfl_xor_sync(0xffffffffu, rs1, 1);
        rs1 += __shfl_xor_sync(0xffffffffu, rs1, 2);
        const float corr0 = fast_exp(m0 - mn0), corr1 = fast_exp(m1 - mn1);
        l0 = l0 * corr0 + rs0;  m0 = mn0;
        l1 = l1 * corr1 + rs1;  m1 = mn1;
#pragma unroll
        for (int n = 0; n < 8; n++) {
            of[n][0] *= corr0; of[n][1] *= corr0;
            of[n][2] *= corr1; of[n][3] *= corr1;
        }

        // P -> smem (tf32) for A-fragment reload; per-warp private rows
        __syncwarp();   // prior PV reads of Ps by this warp complete
#pragma unroll
        for (int n = 0; n < 8; n++) {
            uint32_t* p0 = &Ps[ar    ][n * 8 + 2 * qd];
            uint32_t* p1 = &Ps[ar + 8][n * 8 + 2 * qd];
            p0[0] = f2tf(sc[n][0]); p0[1] = f2tf(sc[n][1]);
            p1[0] = f2tf(sc[n][2]); p1[1] = f2tf(sc[n][3]);
        }
        __syncwarp();

        // O += P V  (A = P from Ps, B = V from Vst)
#pragma unroll
        for (int kc = 0; kc < 8; kc++) {
            uint32_t pa0 = Ps[ar    ][kc * 8 + qd];
            uint32_t pa1 = Ps[ar + 8][kc * 8 + qd];
            uint32_t pa2 = Ps[ar    ][kc * 8 + qd + 4];
            uint32_t pa3 = Ps[ar + 8][kc * 8 + qd + 4];
#pragma unroll
            for (int n = 0; n < 8; n++) {
                uint32_t b0 = Vst[n * 8 + g][kc * 8 + qd];
                uint32_t b1 = Vst[n * 8 + g][kc * 8 + qd + 4];
                mma_tf32(of[n], pa0, pa1, pa2, pa3, b0, b1);
            }
        }
    }

    // epilogue
    const float inv0 = 1.f / l0, inv1 = 1.f / l1;
    const size_t row0 = (size_t)(b * T_ + q0 + warp * 16 + g) * E_;
    const size_t row1 = row0 + 8 * E_;
#pragma unroll
    for (int n = 0; n < 8; n++) {
        const int col = h * HD_ + n * 8 + 2 * qd;
        *(float2*)&out[row0 + col] = make_float2(of[n][0] * inv0, of[n][1] * inv0);
        *(float2*)&out[row1 + col] = make_float2(of[n][2] * inv1, of[n][3] * inv1);
    }
}

// ---------------------------------------------------------------------------
// out = LayerNorm(x + y) * g + b   (one block per row, 128 threads)
// ---------------------------------------------------------------------------
__global__ __launch_bounds__(128) void add_ln(
    const float* __restrict__ x, const float* __restrict__ y,
    const float* __restrict__ g, const float* __restrict__ be,
    float* __restrict__ outp)
{
    const int row = blockIdx.x, tid = threadIdx.x;
    const int c4 = tid << 2;
    float4 xv = *(const float4*)&x[(size_t)row * E_ + c4];
    float4 yv = *(const float4*)&y[(size_t)row * E_ + c4];
    float v[4] = {xv.x + yv.x, xv.y + yv.y, xv.z + yv.z, xv.w + yv.w};
    float s = 0.f, q = 0.f;
#pragma unroll
    for (int c = 0; c < 4; c++) { s += v[c]; q = fmaf(v[c], v[c], q); }
    s = warp_sum(s); q = warp_sum(q);
    __shared__ float ws[4], wq[4];
    const int lane = tid & 31, w = tid >> 5;
    if (lane == 0) { ws[w] = s; wq[w] = q; }
    __syncthreads();
    s = ws[0] + ws[1] + ws[2] + ws[3];
    q = wq[0] + wq[1] + wq[2] + wq[3];
    const float mu   = s * (1.f / E_);
    const float var  = q * (1.f / E_) - mu * mu;
    const float rstd = rsqrtf(var + EPS_);
    float4 gv = *(const float4*)&g[c4];
    float4 bv = *(const float4*)&be[c4];
    float4 ov;
    ov.x = (v[0] - mu) * rstd * gv.x + bv.x;
    ov.y = (v[1] - mu) * rstd * gv.y + bv.y;
    ov.z = (v[2] - mu) * rstd * gv.z + bv.z;
    ov.w = (v[3] - mu) * rstd * gv.w + bv.w;
    *(float4*)&outp[(size_t)row * E_ + c4] = ov;
}

// ---------------------------------------------------------------------------
// Batch-norm stats over all 8192 rows, two deterministic stages
// ---------------------------------------------------------------------------
__global__ __launch_bounds__(256) void bn_part(const float* __restrict__ x) {
    const int blk = blockIdx.x, tid = threadIdx.x;
    float s0 = 0.f, q0 = 0.f, s1 = 0.f, q1 = 0.f;
    const size_t rb = (size_t)blk * 64 * E_;
    for (int r = 0; r < 64; r++) {
        float a = x[rb + (size_t)r * E_ + tid];
        float c = x[rb + (size_t)r * E_ + 256 + tid];
        s0 += a; q0 = fmaf(a, a, q0);
        s1 += c; q1 = fmaf(c, c, q1);
    }
    g_bps[blk * E_ + tid] = s0;        g_bpq[blk * E_ + tid] = q0;
    g_bps[blk * E_ + 256 + tid] = s1;  g_bpq[blk * E_ + 256 + tid] = q1;
}

__global__ void bn_final() {
    const int c = blockIdx.x * blockDim.x + threadIdx.x;
    float s = 0.f, q = 0.f;
    for (int p = 0; p < 128; p++) { s += g_bps[p * E_ + c]; q += g_bpq[p * E_ + c]; }
    g_bsum[c] = s; g_bsq[c] = q;
}

// ---------------------------------------------------------------------------
// Gather rep at the 24 tokens per batch: emb = [shared + bn(out), ner]
// ---------------------------------------------------------------------------
__global__ void gather_emb(const float* __restrict__ sh, const float* __restrict__ ner,
                           const int* __restrict__ rs, const int* __restrict__ re,
                           const float* __restrict__ xw)
{
    const int j = blockIdx.x, b = blockIdx.y, d = threadIdx.x;
    const int t = (j < P_) ? rs[b * P_ + j] : re[b * P_ + j - P_];
    float v;
    if (d < E_) {
        float mu   = g_bsum[d] * (1.f / NT_);
        float var  = g_bsq[d] * (1.f / NT_) - mu * mu;
        float rstd = rsqrtf(var + EPS_);
        size_t off = ((size_t)b * T_ + t) * E_ + d;
        v = sh[off] + (xw[off] - mu) * rstd;
    } else {
        v = ner[((size_t)b * T_ + t) * LBL_ + (d - E_)];
    }
    g_emb[(b * NP_ + j) * D_ + d] = v;
}

// M is diag-constructed: extract diagonal once (off-diagonals are exactly 0)
__global__ void mdiag_k(const float* __restrict__ M) {
    const int r = blockIdx.x, d = threadIdx.x;
    g_mdiag[r * D_ + d] = M[((size_t)r * D_ + d) * D_ + d];
}

// ---------------------------------------------------------------------------
// H[b,j] = relu(W1 @ emb + b1), plus its norm. grid 192, 256 threads (8 warps)
// ---------------------------------------------------------------------------
__global__ __launch_bounds__(256) void rel_h(const float* __restrict__ w1,
                                             const float* __restrict__ b1)
{
    __shared__ float es[D_];
    __shared__ float Hs[FF1_];
    __shared__ float wsum[8];
    const int bj = blockIdx.x, tid = threadIdx.x, lane = tid & 31, w = tid >> 5;
    for (int d = tid; d < D_; d += 256) es[d] = g_emb[bj * D_ + d];
    __syncthreads();
    for (int f = w; f < FF1_; f += 8) {
        float acc = 0.f;
        const float* wr = w1 + (size_t)f * D_;
        for (int d = lane; d < D_; d += 32) acc = fmaf(wr[d], es[d], acc);
        acc = warp_sum(acc);
        if (lane == 0) Hs[f] = fmaxf(acc + b1[f], 0.f);
    }
    __syncthreads();
    float hv = Hs[tid];
    g_H[bj * FF1_ + tid] = hv;
    float q = warp_sum(hv * hv);
    if (lane == 0) wsum[w] = q;
    __syncthreads();
    if (tid == 0) {
        float ss = 0.f;
        for (int k = 0; k < 8; k++) ss += wsum[k];
        g_nrm[bj] = fmaxf(sqrtf(ss), 1e-8f);
    }
}

// ---------------------------------------------------------------------------
// Per-pair scores + BCE. grid 2208, 256 threads (8 warps)
// ---------------------------------------------------------------------------
__global__ __launch_bounds__(256) void pair_k(
    const int* __restrict__ rs, const int* __restrict__ re, const int* __restrict__ rq,
    const float* __restrict__ w2, const float* __restrict__ b2)
{
    const int bp = blockIdx.x;
    const int b = bp / NPAIR_, p = bp % NPAIR_;
    int i = 0, rem = p, cnt = NP_ - 1;
    while (rem >= cnt) { rem -= cnt; i++; cnt--; }
    const int j = i + 1 + rem;

    __shared__ float e1[D_], e2[D_], h1s[FF1_], h2s[FF1_];
    __shared__ float sdm[R_], sred[8], sbce[R_];
    __shared__ float scos;
    const int tid = threadIdx.x, lane = tid & 31, w = tid >> 5;
    const int bi = b * NP_ + i, bj = b * NP_ + j;

    for (int d = tid; d < D_; d += 256) { e1[d] = g_emb[bi * D_ + d]; e2[d] = g_emb[bj * D_ + d]; }
    h1s[tid] = g_H[bi * FF1_ + tid];
    h2s[tid] = g_H[bj * FF1_ + tid];
    __syncthreads();

    float pp = warp_sum(h1s[tid] * h2s[tid]);
    if (lane == 0) sred[w] = pp;
    __syncthreads();
    if (tid == 0) {
        float hh = 0.f;
        for (int k = 0; k < 8; k++) hh += sred[k];
        scos = hh / (g_nrm[bi] * g_nrm[bj]);
    }
    for (int r = w; r < R_; r += 8) {
        float acc = 0.f;
        for (int d = lane; d < D_; d += 32)
            acc = fmaf(g_mdiag[r * D_ + d], e1[d] * e2[d], acc);
        acc = warp_sum(acc);
        if (lane == 0) sdm[r] = acc;
    }
    __syncthreads();

    const int ti = (i < P_) ? rs[b * P_ + i] : re[b * P_ + i - P_];
    const int tj = (j < P_) ? rs[b * P_ + j] : re[b * P_ + j - P_];

    for (int r = w; r < R_; r += 8) {
        float acc = 0.f;
        for (int f = lane; f < F2_; f += 32) {
            float v = (f < FF1_)     ? h1s[f]
                    : (f < 2 * FF1_) ? h2s[f - FF1_]
                    : (f == 512)     ? scos
                                     : sdm[f - 513];
            acc = fmaf(w2[r * F2_ + f], v, acc);
        }
        acc = warp_sum(acc);
        if (lane == 0) {
            float z = acc + b2[r];
            float sc = 1.f / (1.f + expf(-z));
            float tgt = 0.f;
            for (int k = 0; k < P_; k++)
                if (ti == rs[b * P_ + k] && tj == re[b * P_ + k] && rq[b * P_ + k] == r)
                    tgt = 1.f;
            float lp = fmaxf(logf(sc), -100.f);
            float l1 = fmaxf(log1pf(-sc), -100.f);
            sbce[r] = -(tgt * lp + (1.f - tgt) * l1);
        }
    }
    __syncthreads();
    if (tid == 0) {
        float s = 0.f;
        for (int r = 0; r < R_; r++) s += sbce[r];
        g_bce[bp] = s * (1.f / R_);
    }
}

__global__ __launch_bounds__(256) void final_red(float* __restrict__ out) {
    const int tid = threadIdx.x, lane = tid & 31, w = tid >> 5;
    float s = 0.f;
    for (int idx = tid; idx < TP_; idx += 256) s += g_bce[idx];
    s = warp_sum(s);
    __shared__ float ws[8];
    if (lane == 0) ws[w] = s;
    __syncthreads();
    if (tid == 0) {
        float t = 0.f;
        for (int k = 0; k < 8; k++) t += ws[k];
        out[0] = t;
    }
}

// ---------------------------------------------------------------------------
// Launch
// ---------------------------------------------------------------------------
extern "C" void kernel_launch(void* const* d_in, const int* in_sizes, int n_in,
                              void* d_out, int out_size)
{
    const float* sh   = (const float*)d_in[0];
    const float* ner  = (const float*)d_in[1];
    const int*   rs   = (const int*)  d_in[2];
    const int*   re   = (const int*)  d_in[3];
    const int*   rq   = (const int*)  d_in[4];
    const float* wqkv = (const float*)d_in[5];
    const float* bqkv = (const float*)d_in[6];
    const float* wo   = (const float*)d_in[7];
    const float* bo   = (const float*)d_in[8];
    const float* g1   = (const float*)d_in[9];
    const float* b1   = (const float*)d_in[10];
    const float* g2   = (const float*)d_in[11];
    const float* b2ln = (const float*)d_in[12];
    const float* w1   = (const float*)d_in[13];
    const float* bf1  = (const float*)d_in[14];
    const float* w2f  = (const float*)d_in[15];
    const float* bf2  = (const float*)d_in[16];
    const float* wr1  = (const float*)d_in[17];
    const float* br1  = (const float*)d_in[18];
    const float* wr2  = (const float*)d_in[19];
    const float* br2  = (const float*)d_in[20];
    const float* Mfull= (const float*)d_in[21];

    cudaFuncSetAttribute(flash_attn_tc, cudaFuncAttributeMaxDynamicSharedMemorySize, FA_SMEM_);

    float *px, *pqkv, *patt, *py, *ph;
    cudaGetSymbolAddress((void**)&px,   g_x);
    cudaGetSymbolAddress((void**)&pqkv, g_qkv);
    cudaGetSymbolAddress((void**)&patt, g_att);
    cudaGetSymbolAddress((void**)&py,   g_y);
    cudaGetSymbolAddress((void**)&ph,   g_h);

    for (int l = 0; l < 2; l++) {
        const float* xin = (l == 0) ? sh : px;
        gemm_tf32<false><<<dim3(QKV_ / 128, NT_ / 128), 256>>>(
            xin, wqkv + (size_t)l * QKV_ * E_, bqkv + l * QKV_, pqkv, NT_, QKV_, E_);
        flash_attn_tc<<<dim3(T_ / 128, NH_, B_), 256, FA_SMEM_>>>(pqkv, patt);
        gemm_tf32<false><<<dim3(E_ / 128, NT_ / 128), 256>>>(
            patt, wo + (size_t)l * E_ * E_, bo + l * E_, py, NT_, E_, E_);
        add_ln<<<NT_, 128>>>(xin, py, g1 + l * E_, b1 + l * E_, px);
        gemm_tf32<true><<<dim3(E_ / 128, NT_ / 128), 256>>>(
            px, w1 + (size_t)l * E_ * E_, bf1 + l * E_, ph, NT_, E_, E_);
        gemm_tf32<false><<<dim3(E_ / 128, NT_ / 128), 256>>>(
            ph, w2f + (size_t)l * E_ * E_, bf2 + l * E_, py, NT_, E_, E_);
        add_ln<<<NT_, 128>>>(px, py, g2 + l * E_, b2ln + l * E_, px);
    }

    bn_part<<<128, 256>>>(px);
    bn_final<<<2, 256>>>();
    gather_emb<<<dim3(NP_, B_), D_>>>(sh, ner, rs, re, px);
    mdiag_k<<<R_, D_>>>(Mfull);
    rel_h<<<B_ * NP_, 256>>>(wr1, br1);
    pair_k<<<TP_, 256>>>(rs, re, rq, wr2, br2);
    final_red<<<1, 256>>>((float*)d_out);
}